// round 3
// baseline (speedup 1.0000x reference)
#include <cuda_runtime.h>
#include <math.h>

#define NN   50000
#define FIN  512
#define HC1  128
#define H1   8
#define C1   16
#define NC   40
#define EE   800000
#define ETOT (EE + NN)   /* 850000 edges incl. self-loops */
#define NEG  0.2f
#define NB   ((NN + 255) / 256)   /* 196 scan blocks */

typedef unsigned long long ull;

// ---------------- scratch (static device globals; no allocation) -------------
__device__ float g_h1  [(size_t)NN * HC1];   // 25.6 MB  x@W1
__device__ float g_out1[(size_t)NN * HC1];   // 25.6 MB  elu(gat1)
__device__ float g_a1s [(size_t)NN * H1];
__device__ float g_a1d [(size_t)NN * H1];
__device__ float g_h2  [(size_t)NN * NC];    // 8 MB
__device__ float g_a2s [NN];
__device__ float g_a2d [NN];
__device__ int   g_deg [NN];                 // zero-initialized; restored by k_scan_fin
__device__ int   g_rowptr[NN + 1];
__device__ int   g_wp  [NN];
__device__ int   g_col [ETOT];
__device__ int   g_is32;                     // monotone flag, no reset needed
__device__ int   g_bsum[256];
__device__ int   g_boff[256];

// ---------------- f32x2 packed math helpers -----------------------------------
__device__ __forceinline__ ull ffma2(ull a, ull b, ull c) {
    ull d;
    asm("fma.rn.f32x2 %0, %1, %2, %3;" : "=l"(d) : "l"(a), "l"(b), "l"(c));
    return d;
}
__device__ __forceinline__ void unpack2(ull v, float& lo, float& hi) {
    asm("mov.b64 {%0, %1}, %2;" : "=f"(lo), "=f"(hi) : "l"(v));
}
__device__ __forceinline__ float sel8(const float v[8], int h) {
    float r = v[0];
    r = (h == 1) ? v[1] : r;  r = (h == 2) ? v[2] : r;
    r = (h == 3) ? v[3] : r;  r = (h == 4) ? v[4] : r;
    r = (h == 5) ? v[5] : r;  r = (h == 6) ? v[6] : r;
    r = (h == 7) ? v[7] : r;
    return r;
}

// ---------------- edge-index dtype handling ----------------------------------
__device__ __forceinline__ int ld_node(const void* ei, int which, int e, int is32) {
    if (is32) return ((const int*)ei)[which * EE + e];
    return (int)(((const long long*)ei)[which * EE + e]);
}

// If the buffer is actually int32, reading it as int64 combines pairs of
// values < 50000 into numbers >= 2^32 almost surely -> flag. Reads only the
// first EE/2 int64 slots = 6.4MB, in-bounds under either true layout.
__global__ void k_detect(const long long* ei) {
    int i = blockIdx.x * blockDim.x + threadIdx.x;
    if (i >= EE / 2) return;
    long long v = ei[i];
    if (v < 0 || v >= NN) atomicOr(&g_is32, 1);
}

__global__ void k_degree(const void* ei) {
    int e = blockIdx.x * blockDim.x + threadIdx.x;
    if (e >= ETOT) return;
    int is32 = g_is32;
    int dst = (e < EE) ? ld_node(ei, 1, e, is32) : (e - EE);
    atomicAdd(&g_deg[dst], 1);
}

// ---- multi-block exclusive scan of g_deg -> g_rowptr / g_wp ------------------
__global__ void k_scan_blk() {
    __shared__ int ws[8];
    int t = threadIdx.x, i = blockIdx.x * 256 + t;
    int lane = t & 31, wid = t >> 5;
    int v = (i < NN) ? g_deg[i] : 0;
#pragma unroll
    for (int off = 16; off >= 1; off >>= 1) v += __shfl_xor_sync(0xffffffffu, v, off);
    if (lane == 0) ws[wid] = v;
    __syncthreads();
    if (t == 0) {
        int s = 0;
#pragma unroll
        for (int j = 0; j < 8; j++) s += ws[j];
        g_bsum[blockIdx.x] = s;
    }
}

__global__ void k_scan_top() {
    __shared__ int sh[256];
    int t = threadIdx.x;
    int v = (t < NB) ? g_bsum[t] : 0;
    sh[t] = v;
    __syncthreads();
#pragma unroll
    for (int off = 1; off < 256; off <<= 1) {
        int u = (t >= off) ? sh[t - off] : 0;
        __syncthreads();
        sh[t] += u;
        __syncthreads();
    }
    g_boff[t] = sh[t] - v;   // exclusive
    if (t == 0) g_rowptr[NN] = ETOT;
}

__global__ void k_scan_fin() {
    __shared__ int wsum[8];
    int t = threadIdx.x, i = blockIdx.x * 256 + t;
    int lane = t & 31, wid = t >> 5;
    int d = (i < NN) ? g_deg[i] : 0;
    int incl = d;
#pragma unroll
    for (int off = 1; off < 32; off <<= 1) {
        int n = __shfl_up_sync(0xffffffffu, incl, off);
        if (lane >= off) incl += n;
    }
    if (lane == 31) wsum[wid] = incl;
    __syncthreads();
    if (t == 0) {
        int run = 0;
#pragma unroll
        for (int j = 0; j < 8; j++) { int tmp = wsum[j]; wsum[j] = run; run += tmp; }
    }
    __syncthreads();
    int excl = g_boff[blockIdx.x] + wsum[wid] + incl - d;
    if (i < NN) {
        g_rowptr[i] = excl;
        g_wp[i]     = excl;
        g_deg[i]    = 0;     // restore invariant for next replay
    }
}

__global__ void k_scatter(const void* ei) {
    int e = blockIdx.x * blockDim.x + threadIdx.x;
    if (e >= ETOT) return;
    int is32 = g_is32;
    int src, dst;
    if (e < EE) { src = ld_node(ei, 0, e, is32); dst = ld_node(ei, 1, e, is32); }
    else        { src = e - EE; dst = src; }
    int pos = atomicAdd(&g_wp[dst], 1);
    g_col[pos] = src;
}

// ---------------- GEMM1 + fused attn dots -------------------------------------
// h1[N,128] = x[N,512] @ W1[512,128]; also a1s/a1d = einsum(h1, att).
// BM=128, BN=128, BK=16, 256 threads, 8x8 micro-tile, f32x2 packed.
// x tile stored TRANSPOSED+DUPLICATED so LDS yields pre-packed (r,r) pairs;
// W pairs are naturally contiguous. Inner loop: 32 FFMA2 + 6 LDS, no packs.
__global__ __launch_bounds__(256, 2) void k_gemm1(const float* __restrict__ x,
                                                  const float* __restrict__ W1,
                                                  const float* __restrict__ as1,
                                                  const float* __restrict__ ad1) {
    __shared__ float sxD[16][264];    // [k][2*row (+dup)] pitch 264 (16B-aligned)
    __shared__ float sw [16][128];    // [k][col]
    int bm  = blockIdx.x * 128;
    int tid = threadIdx.x;
    int tx = tid & 15;                // col group (8 cols each)
    int ty = tid >> 4;                // row group (8 rows each)

    ull acc[8][4];
#pragma unroll
    for (int i = 0; i < 8; i++)
#pragma unroll
        for (int j = 0; j < 4; j++) acc[i][j] = 0ULL;

    int ldr  = tid >> 1;              // row this thread loads (2 threads/row)
    int ldk  = (tid & 1) * 8;         // k-offset within BK
    int lgrow = bm + ldr;

    for (int k0 = 0; k0 < FIN; k0 += 16) {
        {
            float4 v0 = make_float4(0,0,0,0), v1 = v0;
            if (lgrow < NN) {
                const float4* p = (const float4*)(x + (size_t)lgrow * FIN + k0 + ldk);
                v0 = p[0]; v1 = p[1];
            }
            int r2 = 2 * ldr;
            sxD[ldk + 0][r2] = v0.x; sxD[ldk + 0][r2 + 1] = v0.x;
            sxD[ldk + 1][r2] = v0.y; sxD[ldk + 1][r2 + 1] = v0.y;
            sxD[ldk + 2][r2] = v0.z; sxD[ldk + 2][r2 + 1] = v0.z;
            sxD[ldk + 3][r2] = v0.w; sxD[ldk + 3][r2 + 1] = v0.w;
            sxD[ldk + 4][r2] = v1.x; sxD[ldk + 4][r2 + 1] = v1.x;
            sxD[ldk + 5][r2] = v1.y; sxD[ldk + 5][r2 + 1] = v1.y;
            sxD[ldk + 6][r2] = v1.z; sxD[ldk + 6][r2 + 1] = v1.z;
            sxD[ldk + 7][r2] = v1.w; sxD[ldk + 7][r2 + 1] = v1.w;
        }
#pragma unroll
        for (int q = 0; q < 2; q++) {
            int idx = tid * 2 + q;           // 512 float4s over 16x128 tile
            int rw = idx >> 5;
            int cw = (idx & 31) * 4;
            *(float4*)&sw[rw][cw] = *(const float4*)(W1 + (size_t)(k0 + rw) * HC1 + cw);
        }
        __syncthreads();

#pragma unroll
        for (int k = 0; k < 16; k++) {
            ulonglong2 xa = *(ulonglong2*)&sxD[k][ty * 16];
            ulonglong2 xb = *(ulonglong2*)&sxD[k][ty * 16 + 4];
            ulonglong2 xc = *(ulonglong2*)&sxD[k][ty * 16 + 8];
            ulonglong2 xd = *(ulonglong2*)&sxD[k][ty * 16 + 12];
            ulonglong2 wa = *(ulonglong2*)&sw[k][tx * 8];
            ulonglong2 wb = *(ulonglong2*)&sw[k][tx * 8 + 4];
            ull xp[8] = {xa.x, xa.y, xb.x, xb.y, xc.x, xc.y, xd.x, xd.y};
            ull wp_[4] = {wa.x, wa.y, wb.x, wb.y};
#pragma unroll
            for (int i = 0; i < 8; i++)
#pragma unroll
                for (int j = 0; j < 4; j++)
                    acc[i][j] = ffma2(xp[i], wp_[j], acc[i][j]);
        }
        __syncthreads();
    }

    // epilogue: store h1 + fused attention dots
    int head = tx >> 1;
    int coff = (tx & 1) * 8;
    float avs[8], avd[8];
#pragma unroll
    for (int c = 0; c < 8; c++) {
        avs[c] = as1[head * C1 + coff + c];
        avd[c] = ad1[head * C1 + coff + c];
    }
#pragma unroll
    for (int i = 0; i < 8; i++) {
        int grow = bm + ty * 8 + i;
        float o[8];
#pragma unroll
        for (int j = 0; j < 4; j++) unpack2(acc[i][j], o[2 * j], o[2 * j + 1]);
        if (grow < NN) {
            float* p = g_h1 + (size_t)grow * HC1 + tx * 8;
            *(float4*)p       = make_float4(o[0], o[1], o[2], o[3]);
            *(float4*)(p + 4) = make_float4(o[4], o[5], o[6], o[7]);
        }
        float ps = 0.f, pd = 0.f;
#pragma unroll
        for (int c = 0; c < 8; c++) { ps += o[c] * avs[c]; pd += o[c] * avd[c]; }
        ps += __shfl_xor_sync(0xffffffffu, ps, 1);
        pd += __shfl_xor_sync(0xffffffffu, pd, 1);
        if ((tx & 1) == 0 && grow < NN) {
            g_a1s[grow * H1 + head] = ps;
            g_a1d[grow * H1 + head] = pd;
        }
    }
}

// ---------------- layer-1 edge softmax + aggregation + ELU (warp per dst) -----
// No max pass (logits analytically bounded); exp recomputed in agg pass.
__global__ void k_edge1(const float* __restrict__ b1) {
    int dst  = (blockIdx.x * blockDim.x + threadIdx.x) >> 5;
    int lane = threadIdx.x & 31;
    if (dst >= NN) return;
    int row = g_rowptr[dst];
    int deg = g_rowptr[dst + 1] - row;
    int h = lane >> 2;

    float ad[8];
    {
        const float4* p = (const float4*)(g_a1d + (size_t)dst * H1);
        float4 A = p[0], B = p[1];
        ad[0] = A.x; ad[1] = A.y; ad[2] = A.z; ad[3] = A.w;
        ad[4] = B.x; ad[5] = B.y; ad[6] = B.z; ad[7] = B.w;
    }

    // pass A: denominators
    float sm[8];
#pragma unroll
    for (int hh = 0; hh < 8; hh++) sm[hh] = 0.f;
    for (int j = lane; j < deg; j += 32) {
        int s = g_col[row + j];
        const float4* p = (const float4*)(g_a1s + (size_t)s * H1);
        float4 A = p[0], B = p[1];
        float ev[8] = {A.x + ad[0], A.y + ad[1], A.z + ad[2], A.w + ad[3],
                       B.x + ad[4], B.y + ad[5], B.z + ad[6], B.w + ad[7]};
#pragma unroll
        for (int hh = 0; hh < 8; hh++) {
            float e = ev[hh]; e = e > 0.f ? e : NEG * e;
            sm[hh] += __expf(e);
        }
    }
#pragma unroll
    for (int hh = 0; hh < 8; hh++)
#pragma unroll
        for (int off = 16; off >= 1; off >>= 1)
            sm[hh] += __shfl_xor_sync(0xffffffffu, sm[hh], off);

    float inv = 1.0f / (sel8(sm, h) + 1e-16f);
    float adh = sel8(ad, h);

    // pass B: aggregate (alpha recomputed per edge)
    float4 acc = make_float4(0, 0, 0, 0);
#pragma unroll 2
    for (int j = 0; j < deg; j++) {
        int s = g_col[row + j];
        float e = g_a1s[(size_t)s * H1 + h] + adh;
        e = e > 0.f ? e : NEG * e;
        float al = __expf(e) * inv;
        float4 v = *(const float4*)(g_h1 + (size_t)s * HC1 + lane * 4);
        acc.x += v.x * al; acc.y += v.y * al; acc.z += v.z * al; acc.w += v.w * al;
    }
    int c = lane * 4;
    float4 b = *(const float4*)(b1 + c);
    float o0 = acc.x + b.x, o1 = acc.y + b.y, o2 = acc.z + b.z, o3 = acc.w + b.w;
    o0 = o0 > 0.f ? o0 : expm1f(o0);
    o1 = o1 > 0.f ? o1 : expm1f(o1);
    o2 = o2 > 0.f ? o2 : expm1f(o2);
    o3 = o3 > 0.f ? o3 : expm1f(o3);
    *(float4*)(g_out1 + (size_t)dst * HC1 + c) = make_float4(o0, o1, o2, o3);
}

// ---------------- GEMM2 + fused attn dots -------------------------------------
// h2[N,40] = out1[N,128] @ W2[128,40]; a2s/a2d fused via 8-lane shfl reduce.
__global__ void k_gemm2(const float* __restrict__ W2,
                        const float* __restrict__ as2,
                        const float* __restrict__ ad2) {
    __shared__ float shh[64][65];
    __shared__ float sww[64][NC];
    int bm  = blockIdx.x * 64;
    int tid = threadIdx.x;               // 128 threads
    int rg = tid >> 3, cg = tid & 7;
    float acc[4][5];
#pragma unroll
    for (int i = 0; i < 4; i++)
#pragma unroll
        for (int j = 0; j < 5; j++) acc[i][j] = 0.f;

    for (int k0 = 0; k0 < HC1; k0 += 64) {
#pragma unroll
        for (int it = 0; it < 8; it++) {
            int idx = tid + it * 128;    // float4 index over 64x64 tile
            int r = idx >> 4;
            int kk = (idx & 15) * 4;
            int grow = bm + r;
            float4 v = make_float4(0, 0, 0, 0);
            if (grow < NN) v = *(const float4*)(g_out1 + (size_t)grow * HC1 + k0 + kk);
            shh[r][kk] = v.x; shh[r][kk + 1] = v.y; shh[r][kk + 2] = v.z; shh[r][kk + 3] = v.w;
        }
#pragma unroll
        for (int it = 0; it < 20; it++) {
            int idx = tid + it * 128;    // 64x40 = 2560
            int rw = idx / NC, cw = idx % NC;
            sww[rw][cw] = W2[(size_t)(k0 + rw) * NC + cw];
        }
        __syncthreads();
#pragma unroll 8
        for (int k = 0; k < 64; k++) {
            float hr[4], wr[5];
#pragma unroll
            for (int i = 0; i < 4; i++) hr[i] = shh[rg * 4 + i][k];
#pragma unroll
            for (int j = 0; j < 5; j++) wr[j] = sww[k][cg + 8 * j];
#pragma unroll
            for (int i = 0; i < 4; i++)
#pragma unroll
                for (int j = 0; j < 5; j++) acc[i][j] += hr[i] * wr[j];
        }
        __syncthreads();
    }

    float a2sv[5], a2dv[5];
#pragma unroll
    for (int j = 0; j < 5; j++) { a2sv[j] = as2[cg + 8 * j]; a2dv[j] = ad2[cg + 8 * j]; }

#pragma unroll
    for (int i = 0; i < 4; i++) {
        int grow = bm + rg * 4 + i;
        if (grow < NN) {
#pragma unroll
            for (int j = 0; j < 5; j++)
                g_h2[(size_t)grow * NC + cg + 8 * j] = acc[i][j];
        }
        float ps = 0.f, pd = 0.f;
#pragma unroll
        for (int j = 0; j < 5; j++) { ps += acc[i][j] * a2sv[j]; pd += acc[i][j] * a2dv[j]; }
#pragma unroll
        for (int off = 1; off <= 4; off <<= 1) {
            ps += __shfl_xor_sync(0xffffffffu, ps, off);
            pd += __shfl_xor_sync(0xffffffffu, pd, off);
        }
        if (cg == 0 && grow < NN) { g_a2s[grow] = ps; g_a2d[grow] = pd; }
    }
}

// ---------------- layer-2 edge softmax + aggregation + log_softmax ------------
__global__ void k_edge2(const float* __restrict__ b2, float* __restrict__ out) {
    int dst  = (blockIdx.x * blockDim.x + threadIdx.x) >> 5;
    int lane = threadIdx.x & 31;
    if (dst >= NN) return;
    int row = g_rowptr[dst];
    int deg = g_rowptr[dst + 1] - row;
    float adv = g_a2d[dst];

    float sm = 0.f;
    for (int j = lane; j < deg; j += 32) {
        int s = g_col[row + j];
        float e = g_a2s[s] + adv; e = e > 0.f ? e : NEG * e;
        sm += __expf(e);
    }
#pragma unroll
    for (int off = 16; off >= 1; off >>= 1)
        sm += __shfl_xor_sync(0xffffffffu, sm, off);
    float inv = 1.0f / (sm + 1e-16f);

    float acc0 = 0.f, acc1 = 0.f;
#pragma unroll 2
    for (int j = 0; j < deg; j++) {
        int s = g_col[row + j];
        float e = g_a2s[s] + adv; e = e > 0.f ? e : NEG * e;
        float al = __expf(e) * inv;
        acc0 += g_h2[(size_t)s * NC + lane] * al;
        if (lane < 8) acc1 += g_h2[(size_t)s * NC + 32 + lane] * al;
    }
    acc0 += b2[lane];
    if (lane < 8) acc1 += b2[32 + lane];

    float vm = (lane < 8) ? fmaxf(acc0, acc1) : acc0;
#pragma unroll
    for (int off = 16; off >= 1; off >>= 1)
        vm = fmaxf(vm, __shfl_xor_sync(0xffffffffu, vm, off));
    float se = __expf(acc0 - vm) + ((lane < 8) ? __expf(acc1 - vm) : 0.f);
#pragma unroll
    for (int off = 16; off >= 1; off >>= 1)
        se += __shfl_xor_sync(0xffffffffu, se, off);
    float lse = vm + __logf(se);

    out[(size_t)dst * NC + lane] = acc0 - lse;
    if (lane < 8) out[(size_t)dst * NC + 32 + lane] = acc1 - lse;
}

// ---------------- host ---------------------------------------------------------
extern "C" void kernel_launch(void* const* d_in, const int* in_sizes, int n_in,
                              void* d_out, int out_size) {
    const float* x   = (const float*)d_in[0];
    const void*  ei  = d_in[1];
    const float* W1  = (const float*)d_in[2];
    const float* as1 = (const float*)d_in[3];
    const float* ad1 = (const float*)d_in[4];
    const float* b1  = (const float*)d_in[5];
    const float* W2  = (const float*)d_in[6];
    const float* as2 = (const float*)d_in[7];
    const float* ad2 = (const float*)d_in[8];
    const float* b2  = (const float*)d_in[9];
    float* out = (float*)d_out;

    k_detect  <<<(EE / 2 + 255) / 256, 256>>>((const long long*)ei);
    k_degree  <<<(ETOT + 255) / 256, 256>>>(ei);
    k_scan_blk<<<NB, 256>>>();
    k_scan_top<<<1, 256>>>();
    k_scan_fin<<<NB, 256>>>();
    k_scatter <<<(ETOT + 255) / 256, 256>>>(ei);

    k_gemm1   <<<(NN + 127) / 128, 256>>>(x, W1, as1, ad1);
    k_edge1   <<<(NN * 32 + 255) / 256, 256>>>(b1);

    k_gemm2   <<<(NN + 63) / 64, 128>>>(W2, as2, ad2);
    k_edge2   <<<(NN * 32 + 255) / 256, 256>>>(b2, out);
}

// round 4
// speedup vs baseline: 1.0775x; 1.0775x over previous
#include <cuda_runtime.h>
#include <math.h>

#define NN   50000
#define FIN  512
#define HC1  128
#define H1   8
#define C1   16
#define NC   40
#define EE   800000
#define ETOT (EE + NN)   /* 850000 edges incl. self-loops */
#define NEG  0.2f
#define NB   ((NN + 255) / 256)   /* 196 scan blocks */

typedef unsigned long long ull;

// ---------------- scratch (static device globals; no allocation) -------------
__device__ float g_h1  [(size_t)NN * HC1];   // 25.6 MB  x@W1
__device__ float g_out1[(size_t)NN * HC1];   // 25.6 MB  elu(gat1)
__device__ float g_a1s [(size_t)NN * H1];
__device__ float g_a1d [(size_t)NN * H1];
__device__ float g_h2  [(size_t)NN * NC];    // 8 MB
__device__ float g_a2s [NN];
__device__ float g_a2d [NN];
__device__ int   g_deg [NN];                 // zero-initialized; restored by k_scan_fin
__device__ int   g_rowptr[NN + 1];
__device__ int   g_wp  [NN];
__device__ int   g_col [ETOT];
__device__ int   g_is32;                     // monotone flag, no reset needed
__device__ int   g_bsum[256];
__device__ int   g_boff[256];

// ---------------- f32x2 packed math helpers -----------------------------------
__device__ __forceinline__ ull ffma2(ull a, ull b, ull c) {
    ull d;
    asm("fma.rn.f32x2 %0, %1, %2, %3;" : "=l"(d) : "l"(a), "l"(b), "l"(c));
    return d;
}
__device__ __forceinline__ ull pack2(float lo, float hi) {
    ull d;
    asm("mov.b64 %0, {%1, %2};" : "=l"(d) : "f"(lo), "f"(hi));
    return d;
}
__device__ __forceinline__ void unpack2(ull v, float& lo, float& hi) {
    asm("mov.b64 {%0, %1}, %2;" : "=f"(lo), "=f"(hi) : "l"(v));
}
__device__ __forceinline__ float sel8(const float v[8], int h) {
    float r = v[0];
    r = (h == 1) ? v[1] : r;  r = (h == 2) ? v[2] : r;
    r = (h == 3) ? v[3] : r;  r = (h == 4) ? v[4] : r;
    r = (h == 5) ? v[5] : r;  r = (h == 6) ? v[6] : r;
    r = (h == 7) ? v[7] : r;
    return r;
}

// ---------------- edge-index dtype handling ----------------------------------
__device__ __forceinline__ int ld_node(const void* ei, int which, int e, int is32) {
    if (is32) return ((const int*)ei)[which * EE + e];
    return (int)(((const long long*)ei)[which * EE + e]);
}

// If the buffer is actually int32, reading it as int64 combines pairs of
// values < 50000 into numbers >= 2^32 almost surely -> flag. Reads only the
// first EE/2 int64 slots = 6.4MB, in-bounds under either true layout.
__global__ void k_detect(const long long* ei) {
    int i = blockIdx.x * blockDim.x + threadIdx.x;
    if (i >= EE / 2) return;
    long long v = ei[i];
    if (v < 0 || v >= NN) atomicOr(&g_is32, 1);
}

__global__ void k_degree(const void* ei) {
    int e = blockIdx.x * blockDim.x + threadIdx.x;
    if (e >= ETOT) return;
    int is32 = g_is32;
    int dst = (e < EE) ? ld_node(ei, 1, e, is32) : (e - EE);
    atomicAdd(&g_deg[dst], 1);
}

// ---- multi-block exclusive scan of g_deg -> g_rowptr / g_wp ------------------
__global__ void k_scan_blk() {
    __shared__ int ws[8];
    int t = threadIdx.x, i = blockIdx.x * 256 + t;
    int lane = t & 31, wid = t >> 5;
    int v = (i < NN) ? g_deg[i] : 0;
#pragma unroll
    for (int off = 16; off >= 1; off >>= 1) v += __shfl_xor_sync(0xffffffffu, v, off);
    if (lane == 0) ws[wid] = v;
    __syncthreads();
    if (t == 0) {
        int s = 0;
#pragma unroll
        for (int j = 0; j < 8; j++) s += ws[j];
        g_bsum[blockIdx.x] = s;
    }
}

__global__ void k_scan_top() {
    __shared__ int sh[256];
    int t = threadIdx.x;
    int v = (t < NB) ? g_bsum[t] : 0;
    sh[t] = v;
    __syncthreads();
#pragma unroll
    for (int off = 1; off < 256; off <<= 1) {
        int u = (t >= off) ? sh[t - off] : 0;
        __syncthreads();
        sh[t] += u;
        __syncthreads();
    }
    g_boff[t] = sh[t] - v;   // exclusive
    if (t == 0) g_rowptr[NN] = ETOT;
}

__global__ void k_scan_fin() {
    __shared__ int wsum[8];
    int t = threadIdx.x, i = blockIdx.x * 256 + t;
    int lane = t & 31, wid = t >> 5;
    int d = (i < NN) ? g_deg[i] : 0;
    int incl = d;
#pragma unroll
    for (int off = 1; off < 32; off <<= 1) {
        int n = __shfl_up_sync(0xffffffffu, incl, off);
        if (lane >= off) incl += n;
    }
    if (lane == 31) wsum[wid] = incl;
    __syncthreads();
    if (t == 0) {
        int run = 0;
#pragma unroll
        for (int j = 0; j < 8; j++) { int tmp = wsum[j]; wsum[j] = run; run += tmp; }
    }
    __syncthreads();
    int excl = g_boff[blockIdx.x] + wsum[wid] + incl - d;
    if (i < NN) {
        g_rowptr[i] = excl;
        g_wp[i]     = excl;
        g_deg[i]    = 0;     // restore invariant for next replay
    }
}

__global__ void k_scatter(const void* ei) {
    int e = blockIdx.x * blockDim.x + threadIdx.x;
    if (e >= ETOT) return;
    int is32 = g_is32;
    int src, dst;
    if (e < EE) { src = ld_node(ei, 0, e, is32); dst = ld_node(ei, 1, e, is32); }
    else        { src = e - EE; dst = src; }
    int pos = atomicAdd(&g_wp[dst], 1);
    g_col[pos] = src;
}

// ---------------- GEMM1 + fused attn dots -------------------------------------
// h1[N,128] = x[N,512] @ W1[512,128]; also a1s/a1d = einsum(h1, att).
// BM=128, BN=128, BK=32, 256 threads, 8x8 micro-tile, f32x2 packed.
// (R2-measured structure; fused attention epilogue only.)
__global__ __launch_bounds__(256) void k_gemm1(const float* __restrict__ x,
                                               const float* __restrict__ W1,
                                               const float* __restrict__ as1,
                                               const float* __restrict__ ad1) {
    __shared__ float sxT[32][132];    // [k][row], row pitch 132 (16B-aligned)
    __shared__ float sw [32][128];    // [k][col]
    int bm  = blockIdx.x * 128;
    int tid = threadIdx.x;
    int tx = tid & 15;                // col group (8 cols each)
    int ty = tid >> 4;                // row group (8 rows each)

    ull acc[8][4];                    // 8 rows x 4 col-pairs
#pragma unroll
    for (int i = 0; i < 8; i++)
#pragma unroll
        for (int j = 0; j < 4; j++) acc[i][j] = 0ULL;

    int ldr  = tid >> 1;              // row this thread loads (2 threads/row)
    int ldc0 = (tid & 1) * 16;        // k-offset within BK
    int lgrow = bm + ldr;

    for (int k0 = 0; k0 < FIN; k0 += 32) {
        // x tile (transposed write): 128 rows x 32 k
        {
            float4 v0 = make_float4(0,0,0,0), v1 = v0, v2 = v0, v3 = v0;
            if (lgrow < NN) {
                const float4* p = (const float4*)(x + (size_t)lgrow * FIN + k0 + ldc0);
                v0 = p[0]; v1 = p[1]; v2 = p[2]; v3 = p[3];
            }
            sxT[ldc0 +  0][ldr] = v0.x; sxT[ldc0 +  1][ldr] = v0.y;
            sxT[ldc0 +  2][ldr] = v0.z; sxT[ldc0 +  3][ldr] = v0.w;
            sxT[ldc0 +  4][ldr] = v1.x; sxT[ldc0 +  5][ldr] = v1.y;
            sxT[ldc0 +  6][ldr] = v1.z; sxT[ldc0 +  7][ldr] = v1.w;
            sxT[ldc0 +  8][ldr] = v2.x; sxT[ldc0 +  9][ldr] = v2.y;
            sxT[ldc0 + 10][ldr] = v2.z; sxT[ldc0 + 11][ldr] = v2.w;
            sxT[ldc0 + 12][ldr] = v3.x; sxT[ldc0 + 13][ldr] = v3.y;
            sxT[ldc0 + 14][ldr] = v3.z; sxT[ldc0 + 15][ldr] = v3.w;
        }
        // W tile: 32 k x 128 cols
#pragma unroll
        for (int it = 0; it < 4; it++) {
            int idx = tid + it * 256;
            int rw = idx >> 5;
            int cw = (idx & 31) * 4;
            *(float4*)&sw[rw][cw] = *(const float4*)(W1 + (size_t)(k0 + rw) * HC1 + cw);
        }
        __syncthreads();

#pragma unroll
        for (int k = 0; k < 32; k++) {
            float4 xa = *(float4*)&sxT[k][ty * 8];
            float4 xb = *(float4*)&sxT[k][ty * 8 + 4];
            ull xp[8];
            xp[0] = pack2(xa.x, xa.x); xp[1] = pack2(xa.y, xa.y);
            xp[2] = pack2(xa.z, xa.z); xp[3] = pack2(xa.w, xa.w);
            xp[4] = pack2(xb.x, xb.x); xp[5] = pack2(xb.y, xb.y);
            xp[6] = pack2(xb.z, xb.z); xp[7] = pack2(xb.w, xb.w);
            ull wp_[4];
#pragma unroll
            for (int j = 0; j < 4; j++)
                wp_[j] = *(const ull*)&sw[k][tx * 8 + 2 * j];
#pragma unroll
            for (int i = 0; i < 8; i++)
#pragma unroll
                for (int j = 0; j < 4; j++)
                    acc[i][j] = ffma2(xp[i], wp_[j], acc[i][j]);
        }
        __syncthreads();
    }

    // epilogue: store h1 + fused attention dots
    int head = tx >> 1;
    int coff = (tx & 1) * 8;
    float avs[8], avd[8];
#pragma unroll
    for (int c = 0; c < 8; c++) {
        avs[c] = as1[head * C1 + coff + c];
        avd[c] = ad1[head * C1 + coff + c];
    }
#pragma unroll
    for (int i = 0; i < 8; i++) {
        int grow = bm + ty * 8 + i;
        float o[8];
#pragma unroll
        for (int j = 0; j < 4; j++) unpack2(acc[i][j], o[2 * j], o[2 * j + 1]);
        if (grow < NN) {
            float* p = g_h1 + (size_t)grow * HC1 + tx * 8;
            *(float4*)p       = make_float4(o[0], o[1], o[2], o[3]);
            *(float4*)(p + 4) = make_float4(o[4], o[5], o[6], o[7]);
        }
        float ps = 0.f, pd = 0.f;
#pragma unroll
        for (int c = 0; c < 8; c++) { ps += o[c] * avs[c]; pd += o[c] * avd[c]; }
        ps += __shfl_xor_sync(0xffffffffu, ps, 1);
        pd += __shfl_xor_sync(0xffffffffu, pd, 1);
        if ((tx & 1) == 0 && grow < NN) {
            g_a1s[grow * H1 + head] = ps;
            g_a1d[grow * H1 + head] = pd;
        }
    }
}

// ---------------- layer-1 edge softmax + aggregation + ELU (warp per dst) -----
// No max pass (logits analytically bounded); exp recomputed in agg pass.
__global__ void k_edge1(const float* __restrict__ b1) {
    int dst  = (blockIdx.x * blockDim.x + threadIdx.x) >> 5;
    int lane = threadIdx.x & 31;
    if (dst >= NN) return;
    int row = g_rowptr[dst];
    int deg = g_rowptr[dst + 1] - row;
    int h = lane >> 2;

    float ad[8];
    {
        const float4* p = (const float4*)(g_a1d + (size_t)dst * H1);
        float4 A = p[0], B = p[1];
        ad[0] = A.x; ad[1] = A.y; ad[2] = A.z; ad[3] = A.w;
        ad[4] = B.x; ad[5] = B.y; ad[6] = B.z; ad[7] = B.w;
    }

    // pass A: denominators
    float sm[8];
#pragma unroll
    for (int hh = 0; hh < 8; hh++) sm[hh] = 0.f;
    for (int j = lane; j < deg; j += 32) {
        int s = g_col[row + j];
        const float4* p = (const float4*)(g_a1s + (size_t)s * H1);
        float4 A = p[0], B = p[1];
        float ev[8] = {A.x + ad[0], A.y + ad[1], A.z + ad[2], A.w + ad[3],
                       B.x + ad[4], B.y + ad[5], B.z + ad[6], B.w + ad[7]};
#pragma unroll
        for (int hh = 0; hh < 8; hh++) {
            float e = ev[hh]; e = e > 0.f ? e : NEG * e;
            sm[hh] += __expf(e);
        }
    }
#pragma unroll
    for (int hh = 0; hh < 8; hh++)
#pragma unroll
        for (int off = 16; off >= 1; off >>= 1)
            sm[hh] += __shfl_xor_sync(0xffffffffu, sm[hh], off);

    float inv = 1.0f / (sel8(sm, h) + 1e-16f);
    float adh = sel8(ad, h);

    // pass B: aggregate (alpha recomputed per edge)
    float4 acc = make_float4(0, 0, 0, 0);
#pragma unroll 2
    for (int j = 0; j < deg; j++) {
        int s = g_col[row + j];
        float e = g_a1s[(size_t)s * H1 + h] + adh;
        e = e > 0.f ? e : NEG * e;
        float al = __expf(e) * inv;
        float4 v = *(const float4*)(g_h1 + (size_t)s * HC1 + lane * 4);
        acc.x += v.x * al; acc.y += v.y * al; acc.z += v.z * al; acc.w += v.w * al;
    }
    int c = lane * 4;
    float4 b = *(const float4*)(b1 + c);
    float o0 = acc.x + b.x, o1 = acc.y + b.y, o2 = acc.z + b.z, o3 = acc.w + b.w;
    o0 = o0 > 0.f ? o0 : expm1f(o0);
    o1 = o1 > 0.f ? o1 : expm1f(o1);
    o2 = o2 > 0.f ? o2 : expm1f(o2);
    o3 = o3 > 0.f ? o3 : expm1f(o3);
    *(float4*)(g_out1 + (size_t)dst * HC1 + c) = make_float4(o0, o1, o2, o3);
}

// ---------------- GEMM2 + fused attn dots -------------------------------------
// h2[N,40] = out1[N,128] @ W2[128,40]; a2s/a2d fused via 8-lane shfl reduce.
__global__ void k_gemm2(const float* __restrict__ W2,
                        const float* __restrict__ as2,
                        const float* __restrict__ ad2) {
    __shared__ float shh[64][65];
    __shared__ float sww[64][NC];
    int bm  = blockIdx.x * 64;
    int tid = threadIdx.x;               // 128 threads
    int rg = tid >> 3, cg = tid & 7;
    float acc[4][5];
#pragma unroll
    for (int i = 0; i < 4; i++)
#pragma unroll
        for (int j = 0; j < 5; j++) acc[i][j] = 0.f;

    for (int k0 = 0; k0 < HC1; k0 += 64) {
#pragma unroll
        for (int it = 0; it < 8; it++) {
            int idx = tid + it * 128;    // float4 index over 64x64 tile
            int r = idx >> 4;
            int kk = (idx & 15) * 4;
            int grow = bm + r;
            float4 v = make_float4(0, 0, 0, 0);
            if (grow < NN) v = *(const float4*)(g_out1 + (size_t)grow * HC1 + k0 + kk);
            shh[r][kk] = v.x; shh[r][kk + 1] = v.y; shh[r][kk + 2] = v.z; shh[r][kk + 3] = v.w;
        }
#pragma unroll
        for (int it = 0; it < 20; it++) {
            int idx = tid + it * 128;    // 64x40 = 2560
            int rw = idx / NC, cw = idx % NC;
            sww[rw][cw] = W2[(size_t)(k0 + rw) * NC + cw];
        }
        __syncthreads();
#pragma unroll 8
        for (int k = 0; k < 64; k++) {
            float hr[4], wr[5];
#pragma unroll
            for (int i = 0; i < 4; i++) hr[i] = shh[rg * 4 + i][k];
#pragma unroll
            for (int j = 0; j < 5; j++) wr[j] = sww[k][cg + 8 * j];
#pragma unroll
            for (int i = 0; i < 4; i++)
#pragma unroll
                for (int j = 0; j < 5; j++) acc[i][j] += hr[i] * wr[j];
        }
        __syncthreads();
    }

    float a2sv[5], a2dv[5];
#pragma unroll
    for (int j = 0; j < 5; j++) { a2sv[j] = as2[cg + 8 * j]; a2dv[j] = ad2[cg + 8 * j]; }

#pragma unroll
    for (int i = 0; i < 4; i++) {
        int grow = bm + rg * 4 + i;
        if (grow < NN) {
#pragma unroll
            for (int j = 0; j < 5; j++)
                g_h2[(size_t)grow * NC + cg + 8 * j] = acc[i][j];
        }
        float ps = 0.f, pd = 0.f;
#pragma unroll
        for (int j = 0; j < 5; j++) { ps += acc[i][j] * a2sv[j]; pd += acc[i][j] * a2dv[j]; }
#pragma unroll
        for (int off = 1; off <= 4; off <<= 1) {
            ps += __shfl_xor_sync(0xffffffffu, ps, off);
            pd += __shfl_xor_sync(0xffffffffu, pd, off);
        }
        if (cg == 0 && grow < NN) { g_a2s[grow] = ps; g_a2d[grow] = pd; }
    }
}

// ---------------- layer-2 edge softmax + aggregation + log_softmax ------------
__global__ void k_edge2(const float* __restrict__ b2, float* __restrict__ out) {
    int dst  = (blockIdx.x * blockDim.x + threadIdx.x) >> 5;
    int lane = threadIdx.x & 31;
    if (dst >= NN) return;
    int row = g_rowptr[dst];
    int deg = g_rowptr[dst + 1] - row;
    float adv = g_a2d[dst];

    float sm = 0.f;
    for (int j = lane; j < deg; j += 32) {
        int s = g_col[row + j];
        float e = g_a2s[s] + adv; e = e > 0.f ? e : NEG * e;
        sm += __expf(e);
    }
#pragma unroll
    for (int off = 16; off >= 1; off >>= 1)
        sm += __shfl_xor_sync(0xffffffffu, sm, off);
    float inv = 1.0f / (sm + 1e-16f);

    float acc0 = 0.f, acc1 = 0.f;
#pragma unroll 2
    for (int j = 0; j < deg; j++) {
        int s = g_col[row + j];
        float e = g_a2s[s] + adv; e = e > 0.f ? e : NEG * e;
        float al = __expf(e) * inv;
        acc0 += g_h2[(size_t)s * NC + lane] * al;
        if (lane < 8) acc1 += g_h2[(size_t)s * NC + 32 + lane] * al;
    }
    acc0 += b2[lane];
    if (lane < 8) acc1 += b2[32 + lane];

    float vm = (lane < 8) ? fmaxf(acc0, acc1) : acc0;
#pragma unroll
    for (int off = 16; off >= 1; off >>= 1)
        vm = fmaxf(vm, __shfl_xor_sync(0xffffffffu, vm, off));
    float se = __expf(acc0 - vm) + ((lane < 8) ? __expf(acc1 - vm) : 0.f);
#pragma unroll
    for (int off = 16; off >= 1; off >>= 1)
        se += __shfl_xor_sync(0xffffffffu, se, off);
    float lse = vm + __logf(se);

    out[(size_t)dst * NC + lane] = acc0 - lse;
    if (lane < 8) out[(size_t)dst * NC + 32 + lane] = acc1 - lse;
}

// ---------------- host ---------------------------------------------------------
extern "C" void kernel_launch(void* const* d_in, const int* in_sizes, int n_in,
                              void* d_out, int out_size) {
    const float* x   = (const float*)d_in[0];
    const void*  ei  = d_in[1];
    const float* W1  = (const float*)d_in[2];
    const float* as1 = (const float*)d_in[3];
    const float* ad1 = (const float*)d_in[4];
    const float* b1  = (const float*)d_in[5];
    const float* W2  = (const float*)d_in[6];
    const float* as2 = (const float*)d_in[7];
    const float* ad2 = (const float*)d_in[8];
    const float* b2  = (const float*)d_in[9];
    float* out = (float*)d_out;

    k_detect  <<<(EE / 2 + 255) / 256, 256>>>((const long long*)ei);
    k_degree  <<<(ETOT + 255) / 256, 256>>>(ei);
    k_scan_blk<<<NB, 256>>>();
    k_scan_top<<<1, 256>>>();
    k_scan_fin<<<NB, 256>>>();
    k_scatter <<<(ETOT + 255) / 256, 256>>>(ei);

    k_gemm1   <<<(NN + 127) / 128, 256>>>(x, W1, as1, ad1);
    k_edge1   <<<(NN * 32 + 255) / 256, 256>>>(b1);

    k_gemm2   <<<(NN + 63) / 64, 128>>>(W2, as2, ad2);
    k_edge2   <<<(NN * 32 + 255) / 256, 256>>>(b2, out);
}

// round 5
// speedup vs baseline: 1.1585x; 1.0753x over previous
#include <cuda_runtime.h>
#include <math.h>

#define NN   50000
#define FIN  512
#define HC1  128
#define H1   8
#define C1   16
#define NC   40
#define EE   800000
#define ETOT (EE + NN)   /* 850000 edges incl. self-loops */
#define NEG  0.2f
#define NB   ((NN + 255) / 256)   /* 196 scan blocks */

typedef unsigned long long ull;

// ---------------- scratch (static device globals; no allocation) -------------
__device__ float g_h1  [(size_t)NN * HC1];   // 25.6 MB  x@W1
__device__ float g_out1[(size_t)NN * HC1];   // 25.6 MB  elu(gat1)
__device__ float g_a1s [(size_t)NN * H1];
__device__ float g_a1d [(size_t)NN * H1];
__device__ float g_h2  [(size_t)NN * NC];    // 8 MB
__device__ float g_a2s [NN];
__device__ float g_a2d [NN];
__device__ int   g_deg [NN];                 // zero-initialized; restored by k_scan_fin
__device__ int   g_rowptr[NN + 1];
__device__ int   g_wp  [NN];
__device__ int   g_col [ETOT];
__device__ int   g_is32;                     // monotone flag, no reset needed
__device__ int   g_bsum[256];

// ---------------- f32x2 packed math helpers -----------------------------------
__device__ __forceinline__ ull ffma2(ull a, ull b, ull c) {
    ull d;
    asm("fma.rn.f32x2 %0, %1, %2, %3;" : "=l"(d) : "l"(a), "l"(b), "l"(c));
    return d;
}
__device__ __forceinline__ ull pack2(float lo, float hi) {
    ull d;
    asm("mov.b64 %0, {%1, %2};" : "=l"(d) : "f"(lo), "f"(hi));
    return d;
}
__device__ __forceinline__ void unpack2(ull v, float& lo, float& hi) {
    asm("mov.b64 {%0, %1}, %2;" : "=f"(lo), "=f"(hi) : "l"(v));
}
__device__ __forceinline__ float sel8(const float v[8], int h) {
    float r = v[0];
    r = (h == 1) ? v[1] : r;  r = (h == 2) ? v[2] : r;
    r = (h == 3) ? v[3] : r;  r = (h == 4) ? v[4] : r;
    r = (h == 5) ? v[5] : r;  r = (h == 6) ? v[6] : r;
    r = (h == 7) ? v[7] : r;
    return r;
}

// ---------------- edge-index dtype handling ----------------------------------
__device__ __forceinline__ int ld_node(const void* ei, int which, int e, int is32) {
    if (is32) return ((const int*)ei)[which * EE + e];
    return (int)(((const long long*)ei)[which * EE + e]);
}

// If the buffer is actually int32, reading it as int64 combines pairs of
// values < 50000 into numbers >= 2^32 almost surely -> flag. Reads only the
// first EE/2 int64 slots = 6.4MB, in-bounds under either true layout.
__global__ void k_detect(const long long* ei) {
    int i = blockIdx.x * blockDim.x + threadIdx.x;
    if (i >= EE / 2) return;
    long long v = ei[i];
    if (v < 0 || v >= NN) atomicOr(&g_is32, 1);
}

__global__ void k_degree(const void* ei) {
    int e = blockIdx.x * blockDim.x + threadIdx.x;
    if (e >= ETOT) return;
    int is32 = g_is32;
    int dst = (e < EE) ? ld_node(ei, 1, e, is32) : (e - EE);
    atomicAdd(&g_deg[dst], 1);
}

// ---- 2-kernel exclusive scan of g_deg -> g_rowptr / g_wp ---------------------
__global__ void k_scan_blk() {
    __shared__ int ws[8];
    int t = threadIdx.x, i = blockIdx.x * 256 + t;
    int lane = t & 31, wid = t >> 5;
    int v = (i < NN) ? g_deg[i] : 0;
#pragma unroll
    for (int off = 16; off >= 1; off >>= 1) v += __shfl_xor_sync(0xffffffffu, v, off);
    if (lane == 0) ws[wid] = v;
    __syncthreads();
    if (t == 0) {
        int s = 0;
#pragma unroll
        for (int j = 0; j < 8; j++) s += ws[j];
        g_bsum[blockIdx.x] = s;
    }
}

// Final scan: each block reduces g_bsum[0..bid-1] for its offset, then
// block-local scan. Replaces the old k_scan_top + k_scan_fin pair.
__global__ void k_scan_fin() {
    __shared__ int ws[8];
    __shared__ int wsum[8];
    __shared__ int s_boff;
    int t = threadIdx.x, i = blockIdx.x * 256 + t;
    int lane = t & 31, wid = t >> 5;

    // block offset = sum of preceding block totals
    int pv = (t < (int)blockIdx.x) ? g_bsum[t] : 0;
#pragma unroll
    for (int off = 16; off >= 1; off >>= 1) pv += __shfl_xor_sync(0xffffffffu, pv, off);
    if (lane == 0) ws[wid] = pv;
    __syncthreads();
    if (t == 0) {
        int s = 0;
#pragma unroll
        for (int j = 0; j < 8; j++) s += ws[j];
        s_boff = s;
    }

    int d = (i < NN) ? g_deg[i] : 0;
    int incl = d;
#pragma unroll
    for (int off = 1; off < 32; off <<= 1) {
        int n = __shfl_up_sync(0xffffffffu, incl, off);
        if (lane >= off) incl += n;
    }
    if (lane == 31) wsum[wid] = incl;
    __syncthreads();
    if (t == 0) {
        int run = 0;
#pragma unroll
        for (int j = 0; j < 8; j++) { int tmp = wsum[j]; wsum[j] = run; run += tmp; }
    }
    __syncthreads();
    int excl = s_boff + wsum[wid] + incl - d;
    if (i < NN) {
        g_rowptr[i] = excl;
        g_wp[i]     = excl;
        g_deg[i]    = 0;     // restore invariant for next replay
    }
    if (i == 0) g_rowptr[NN] = ETOT;
}

__global__ void k_scatter(const void* ei) {
    int e = blockIdx.x * blockDim.x + threadIdx.x;
    if (e >= ETOT) return;
    int is32 = g_is32;
    int src, dst;
    if (e < EE) { src = ld_node(ei, 0, e, is32); dst = ld_node(ei, 1, e, is32); }
    else        { src = e - EE; dst = src; }
    int pos = atomicAdd(&g_wp[dst], 1);
    g_col[pos] = src;
}

// ---------------- GEMM1 + fused attn dots -------------------------------------
// h1[N,128] = x[N,512] @ W1[512,128]; also a1s/a1d = einsum(h1, att).
// BM=128, BN=128, BK=32, 256 threads, 8x8 micro-tile, f32x2 packed.
__global__ __launch_bounds__(256) void k_gemm1(const float* __restrict__ x,
                                               const float* __restrict__ W1,
                                               const float* __restrict__ as1,
                                               const float* __restrict__ ad1) {
    __shared__ float sxT[32][132];    // [k][row], row pitch 132 (16B-aligned)
    __shared__ float sw [32][128];    // [k][col]
    int bm  = blockIdx.x * 128;
    int tid = threadIdx.x;
    int tx = tid & 15;                // col group (8 cols each)
    int ty = tid >> 4;                // row group (8 rows each)

    ull acc[8][4];                    // 8 rows x 4 col-pairs
#pragma unroll
    for (int i = 0; i < 8; i++)
#pragma unroll
        for (int j = 0; j < 4; j++) acc[i][j] = 0ULL;

    int ldr  = tid >> 1;              // row this thread loads (2 threads/row)
    int ldc0 = (tid & 1) * 16;        // k-offset within BK
    int lgrow = bm + ldr;

    for (int k0 = 0; k0 < FIN; k0 += 32) {
        // x tile (transposed write): 128 rows x 32 k
        {
            float4 v0 = make_float4(0,0,0,0), v1 = v0, v2 = v0, v3 = v0;
            if (lgrow < NN) {
                const float4* p = (const float4*)(x + (size_t)lgrow * FIN + k0 + ldc0);
                v0 = p[0]; v1 = p[1]; v2 = p[2]; v3 = p[3];
            }
            sxT[ldc0 +  0][ldr] = v0.x; sxT[ldc0 +  1][ldr] = v0.y;
            sxT[ldc0 +  2][ldr] = v0.z; sxT[ldc0 +  3][ldr] = v0.w;
            sxT[ldc0 +  4][ldr] = v1.x; sxT[ldc0 +  5][ldr] = v1.y;
            sxT[ldc0 +  6][ldr] = v1.z; sxT[ldc0 +  7][ldr] = v1.w;
            sxT[ldc0 +  8][ldr] = v2.x; sxT[ldc0 +  9][ldr] = v2.y;
            sxT[ldc0 + 10][ldr] = v2.z; sxT[ldc0 + 11][ldr] = v2.w;
            sxT[ldc0 + 12][ldr] = v3.x; sxT[ldc0 + 13][ldr] = v3.y;
            sxT[ldc0 + 14][ldr] = v3.z; sxT[ldc0 + 15][ldr] = v3.w;
        }
        // W tile: 32 k x 128 cols
#pragma unroll
        for (int it = 0; it < 4; it++) {
            int idx = tid + it * 256;
            int rw = idx >> 5;
            int cw = (idx & 31) * 4;
            *(float4*)&sw[rw][cw] = *(const float4*)(W1 + (size_t)(k0 + rw) * HC1 + cw);
        }
        __syncthreads();

#pragma unroll
        for (int k = 0; k < 32; k++) {
            float4 xa = *(float4*)&sxT[k][ty * 8];
            float4 xb = *(float4*)&sxT[k][ty * 8 + 4];
            ull xp[8];
            xp[0] = pack2(xa.x, xa.x); xp[1] = pack2(xa.y, xa.y);
            xp[2] = pack2(xa.z, xa.z); xp[3] = pack2(xa.w, xa.w);
            xp[4] = pack2(xb.x, xb.x); xp[5] = pack2(xb.y, xb.y);
            xp[6] = pack2(xb.z, xb.z); xp[7] = pack2(xb.w, xb.w);
            ull wp_[4];
#pragma unroll
            for (int j = 0; j < 4; j++)
                wp_[j] = *(const ull*)&sw[k][tx * 8 + 2 * j];
#pragma unroll
            for (int i = 0; i < 8; i++)
#pragma unroll
                for (int j = 0; j < 4; j++)
                    acc[i][j] = ffma2(xp[i], wp_[j], acc[i][j]);
        }
        __syncthreads();
    }

    // epilogue: store h1 + fused attention dots
    int head = tx >> 1;
    int coff = (tx & 1) * 8;
    float avs[8], avd[8];
#pragma unroll
    for (int c = 0; c < 8; c++) {
        avs[c] = as1[head * C1 + coff + c];
        avd[c] = ad1[head * C1 + coff + c];
    }
#pragma unroll
    for (int i = 0; i < 8; i++) {
        int grow = bm + ty * 8 + i;
        float o[8];
#pragma unroll
        for (int j = 0; j < 4; j++) unpack2(acc[i][j], o[2 * j], o[2 * j + 1]);
        if (grow < NN) {
            float* p = g_h1 + (size_t)grow * HC1 + tx * 8;
            *(float4*)p       = make_float4(o[0], o[1], o[2], o[3]);
            *(float4*)(p + 4) = make_float4(o[4], o[5], o[6], o[7]);
        }
        float ps = 0.f, pd = 0.f;
#pragma unroll
        for (int c = 0; c < 8; c++) { ps += o[c] * avs[c]; pd += o[c] * avd[c]; }
        ps += __shfl_xor_sync(0xffffffffu, ps, 1);
        pd += __shfl_xor_sync(0xffffffffu, pd, 1);
        if ((tx & 1) == 0 && grow < NN) {
            g_a1s[grow * H1 + head] = ps;
            g_a1d[grow * H1 + head] = pd;
        }
    }
}

// ---------------- layer-1 edge softmax + aggregation + ELU (warp per dst) -----
__global__ void k_edge1(const float* __restrict__ b1) {
    int dst  = (blockIdx.x * blockDim.x + threadIdx.x) >> 5;
    int lane = threadIdx.x & 31;
    if (dst >= NN) return;
    int row = g_rowptr[dst];
    int deg = g_rowptr[dst + 1] - row;
    int h = lane >> 2;

    float ad[8];
    {
        const float4* p = (const float4*)(g_a1d + (size_t)dst * H1);
        float4 A = p[0], B = p[1];
        ad[0] = A.x; ad[1] = A.y; ad[2] = A.z; ad[3] = A.w;
        ad[4] = B.x; ad[5] = B.y; ad[6] = B.z; ad[7] = B.w;
    }

    // pass A: denominators
    float sm[8];
#pragma unroll
    for (int hh = 0; hh < 8; hh++) sm[hh] = 0.f;
    for (int j = lane; j < deg; j += 32) {
        int s = g_col[row + j];
        const float4* p = (const float4*)(g_a1s + (size_t)s * H1);
        float4 A = p[0], B = p[1];
        float ev[8] = {A.x + ad[0], A.y + ad[1], A.z + ad[2], A.w + ad[3],
                       B.x + ad[4], B.y + ad[5], B.z + ad[6], B.w + ad[7]};
#pragma unroll
        for (int hh = 0; hh < 8; hh++) {
            float e = ev[hh]; e = e > 0.f ? e : NEG * e;
            sm[hh] += __expf(e);
        }
    }
#pragma unroll
    for (int hh = 0; hh < 8; hh++)
#pragma unroll
        for (int off = 16; off >= 1; off >>= 1)
            sm[hh] += __shfl_xor_sync(0xffffffffu, sm[hh], off);

    float inv = 1.0f / (sel8(sm, h) + 1e-16f);
    float adh = sel8(ad, h);

    // pass B: aggregate (alpha recomputed per edge)
    float4 acc = make_float4(0, 0, 0, 0);
#pragma unroll 2
    for (int j = 0; j < deg; j++) {
        int s = g_col[row + j];
        float e = g_a1s[(size_t)s * H1 + h] + adh;
        e = e > 0.f ? e : NEG * e;
        float al = __expf(e) * inv;
        float4 v = *(const float4*)(g_h1 + (size_t)s * HC1 + lane * 4);
        acc.x += v.x * al; acc.y += v.y * al; acc.z += v.z * al; acc.w += v.w * al;
    }
    int c = lane * 4;
    float4 b = *(const float4*)(b1 + c);
    float o0 = acc.x + b.x, o1 = acc.y + b.y, o2 = acc.z + b.z, o3 = acc.w + b.w;
    o0 = o0 > 0.f ? o0 : expm1f(o0);
    o1 = o1 > 0.f ? o1 : expm1f(o1);
    o2 = o2 > 0.f ? o2 : expm1f(o2);
    o3 = o3 > 0.f ? o3 : expm1f(o3);
    *(float4*)(g_out1 + (size_t)dst * HC1 + c) = make_float4(o0, o1, o2, o3);
}

// ---------------- GEMM2 + fused attn dots -------------------------------------
__global__ void k_gemm2(const float* __restrict__ W2,
                        const float* __restrict__ as2,
                        const float* __restrict__ ad2) {
    __shared__ float shh[64][65];
    __shared__ float sww[64][NC];
    int bm  = blockIdx.x * 64;
    int tid = threadIdx.x;               // 128 threads
    int rg = tid >> 3, cg = tid & 7;
    float acc[4][5];
#pragma unroll
    for (int i = 0; i < 4; i++)
#pragma unroll
        for (int j = 0; j < 5; j++) acc[i][j] = 0.f;

    for (int k0 = 0; k0 < HC1; k0 += 64) {
#pragma unroll
        for (int it = 0; it < 8; it++) {
            int idx = tid + it * 128;    // float4 index over 64x64 tile
            int r = idx >> 4;
            int kk = (idx & 15) * 4;
            int grow = bm + r;
            float4 v = make_float4(0, 0, 0, 0);
            if (grow < NN) v = *(const float4*)(g_out1 + (size_t)grow * HC1 + k0 + kk);
            shh[r][kk] = v.x; shh[r][kk + 1] = v.y; shh[r][kk + 2] = v.z; shh[r][kk + 3] = v.w;
        }
#pragma unroll
        for (int it = 0; it < 20; it++) {
            int idx = tid + it * 128;    // 64x40 = 2560
            int rw = idx / NC, cw = idx % NC;
            sww[rw][cw] = W2[(size_t)(k0 + rw) * NC + cw];
        }
        __syncthreads();
#pragma unroll 8
        for (int k = 0; k < 64; k++) {
            float hr[4], wr[5];
#pragma unroll
            for (int i = 0; i < 4; i++) hr[i] = shh[rg * 4 + i][k];
#pragma unroll
            for (int j = 0; j < 5; j++) wr[j] = sww[k][cg + 8 * j];
#pragma unroll
            for (int i = 0; i < 4; i++)
#pragma unroll
                for (int j = 0; j < 5; j++) acc[i][j] += hr[i] * wr[j];
        }
        __syncthreads();
    }

    float a2sv[5], a2dv[5];
#pragma unroll
    for (int j = 0; j < 5; j++) { a2sv[j] = as2[cg + 8 * j]; a2dv[j] = ad2[cg + 8 * j]; }

#pragma unroll
    for (int i = 0; i < 4; i++) {
        int grow = bm + rg * 4 + i;
        if (grow < NN) {
#pragma unroll
            for (int j = 0; j < 5; j++)
                g_h2[(size_t)grow * NC + cg + 8 * j] = acc[i][j];
        }
        float ps = 0.f, pd = 0.f;
#pragma unroll
        for (int j = 0; j < 5; j++) { ps += acc[i][j] * a2sv[j]; pd += acc[i][j] * a2dv[j]; }
#pragma unroll
        for (int off = 1; off <= 4; off <<= 1) {
            ps += __shfl_xor_sync(0xffffffffu, ps, off);
            pd += __shfl_xor_sync(0xffffffffu, pd, off);
        }
        if (cg == 0 && grow < NN) { g_a2s[grow] = ps; g_a2d[grow] = pd; }
    }
}

// ---------------- layer-2 edge softmax + aggregation + log_softmax ------------
__global__ void k_edge2(const float* __restrict__ b2, float* __restrict__ out) {
    int dst  = (blockIdx.x * blockDim.x + threadIdx.x) >> 5;
    int lane = threadIdx.x & 31;
    if (dst >= NN) return;
    int row = g_rowptr[dst];
    int deg = g_rowptr[dst + 1] - row;
    float adv = g_a2d[dst];

    float sm = 0.f;
    for (int j = lane; j < deg; j += 32) {
        int s = g_col[row + j];
        float e = g_a2s[s] + adv; e = e > 0.f ? e : NEG * e;
        sm += __expf(e);
    }
#pragma unroll
    for (int off = 16; off >= 1; off >>= 1)
        sm += __shfl_xor_sync(0xffffffffu, sm, off);
    float inv = 1.0f / (sm + 1e-16f);

    float acc0 = 0.f, acc1 = 0.f;
#pragma unroll 2
    for (int j = 0; j < deg; j++) {
        int s = g_col[row + j];
        float e = g_a2s[s] + adv; e = e > 0.f ? e : NEG * e;
        float al = __expf(e) * inv;
        acc0 += g_h2[(size_t)s * NC + lane] * al;
        if (lane < 8) acc1 += g_h2[(size_t)s * NC + 32 + lane] * al;
    }
    acc0 += b2[lane];
    if (lane < 8) acc1 += b2[32 + lane];

    float vm = (lane < 8) ? fmaxf(acc0, acc1) : acc0;
#pragma unroll
    for (int off = 16; off >= 1; off >>= 1)
        vm = fmaxf(vm, __shfl_xor_sync(0xffffffffu, vm, off));
    float se = __expf(acc0 - vm) + ((lane < 8) ? __expf(acc1 - vm) : 0.f);
#pragma unroll
    for (int off = 16; off >= 1; off >>= 1)
        se += __shfl_xor_sync(0xffffffffu, se, off);
    float lse = vm + __logf(se);

    out[(size_t)dst * NC + lane] = acc0 - lse;
    if (lane < 8) out[(size_t)dst * NC + 32 + lane] = acc1 - lse;
}

// ---------------- host ---------------------------------------------------------
// CSR build runs on a forked stream, concurrent with GEMM1 (no data deps).
static cudaStream_t s_csr = 0;
static cudaEvent_t  ev_fork = 0, ev_join = 0;

extern "C" void kernel_launch(void* const* d_in, const int* in_sizes, int n_in,
                              void* d_out, int out_size) {
    const float* x   = (const float*)d_in[0];
    const void*  ei  = d_in[1];
    const float* W1  = (const float*)d_in[2];
    const float* as1 = (const float*)d_in[3];
    const float* ad1 = (const float*)d_in[4];
    const float* b1  = (const float*)d_in[5];
    const float* W2  = (const float*)d_in[6];
    const float* as2 = (const float*)d_in[7];
    const float* ad2 = (const float*)d_in[8];
    const float* b2  = (const float*)d_in[9];
    float* out = (float*)d_out;

    if (!s_csr) {   // one-time resource creation (first call is uncaptured)
        cudaStreamCreateWithFlags(&s_csr, cudaStreamNonBlocking);
        cudaEventCreateWithFlags(&ev_fork, cudaEventDisableTiming);
        cudaEventCreateWithFlags(&ev_join, cudaEventDisableTiming);
    }

    // fork: CSR chain on s_csr
    cudaEventRecord(ev_fork, 0);
    cudaStreamWaitEvent(s_csr, ev_fork, 0);

    k_detect  <<<(EE / 2 + 255) / 256, 256, 0, s_csr>>>((const long long*)ei);
    k_degree  <<<(ETOT + 255) / 256, 256, 0, s_csr>>>(ei);
    k_scan_blk<<<NB, 256, 0, s_csr>>>();
    k_scan_fin<<<NB, 256, 0, s_csr>>>();
    k_scatter <<<(ETOT + 255) / 256, 256, 0, s_csr>>>(ei);
    cudaEventRecord(ev_join, s_csr);

    // concurrent: GEMM1 on main stream
    k_gemm1   <<<(NN + 127) / 128, 256>>>(x, W1, as1, ad1);

    // join: edge phase needs both CSR and GEMM1
    cudaStreamWaitEvent(0, ev_join, 0);

    k_edge1   <<<(NN * 32 + 255) / 256, 256>>>(b1);
    k_gemm2   <<<(NN + 63) / 64, 128>>>(W2, as2, ad2);
    k_edge2   <<<(NN * 32 + 255) / 256, 256>>>(b2, out);
}